// round 11
// baseline (speedup 1.0000x reference)
#include <cuda_runtime.h>
#include <cuda_fp16.h>
#include <cstdint>

#define N_MAX 100000
#define CIN   64
#define CMID  64
#define COUT  128
#define BN_EPS 1e-5
#define NSLOT 16

// ---------------- mma / ldmatrix helpers (sm_103a HMMA path) ----------------
__device__ __forceinline__ uint32_t smem_u32(const void* p) {
    return (uint32_t)__cvta_generic_to_shared(p);
}
#define LDMX4T(r0, r1, r2, r3, addr) \
    asm volatile("ldmatrix.sync.aligned.m8n8.x4.trans.shared.b16 {%0,%1,%2,%3}, [%4];" \
                 : "=r"(r0), "=r"(r1), "=r"(r2), "=r"(r3) : "r"(addr))
#define MMA16816(d, a0, a1, a2, a3, b0, b1) \
    asm volatile("mma.sync.aligned.m16n8k16.row.col.f32.f16.f16.f32 " \
                 "{%0,%1,%2,%3}, {%4,%5,%6,%7}, {%8,%9}, {%0,%1,%2,%3};" \
                 : "+f"(d[0]), "+f"(d[1]), "+f"(d[2]), "+f"(d[3]) \
                 : "r"(a0), "r"(a1), "r"(a2), "r"(a3), "r"(b0), "r"(b1))

// ---------------- device scratch (static: no allocations allowed) ----------------
__device__ int    g_count[N_MAX];
__device__ __half g_T1h[(size_t)N_MAX * CMID];   // feat @ W1 + b1, fp16 (12.8 MB)
__device__ __half g_T2h[(size_t)N_MAX * COUT];   // T2 pre-BN2, fp16 (25.6 MB)
__device__ double g_sum1[NSLOT * CMID], g_sq1[NSLOT * CMID];
__device__ double g_sum2[NSLOT * COUT], g_sq2[NSLOT * COUT];
__device__ int    g_is64;

// ---------------- K0: zero counters/accumulators + detect idx dtype -------------
// idx in [0, n), n < 2^31. Little-endian int64 => every odd 32-bit word is 0.
__global__ void k_init(const int* w, int nk, int n) {
    int i  = blockIdx.x * blockDim.x + threadIdx.x;
    int st = gridDim.x * blockDim.x;
    for (int j = i; j < n; j += st) g_count[j] = 0;
    if (i < NSLOT * CMID) { g_sum1[i] = 0.0; g_sq1[i] = 0.0; }
    if (i < NSLOT * COUT) { g_sum2[i] = 0.0; g_sq2[i] = 0.0; }
    if (blockIdx.x == 0) {
        __shared__ int ok;
        if (threadIdx.x == 0) ok = 1;
        __syncthreads();
        int m = 64;
        if (nk < 128) m = nk / 2;
        if ((int)threadIdx.x < m) {
            if (w[2 * threadIdx.x + 1] != 0) ok = 0;  // benign race: only writes 0
        }
        __syncthreads();
        if (threadIdx.x == 0) g_is64 = ok;
    }
}

// ---------------- K1: histogram of idx (vectorized int4 loads) ----------------
__global__ void k_hist(const void* idxp, int nk) {
    int is64 = g_is64;
    int i  = blockIdx.x * blockDim.x + threadIdx.x;
    int st = gridDim.x * blockDim.x;
    if ((nk & 3) == 0) {
        const int4* p = (const int4*)idxp;
        if (is64) {
            int nq = nk >> 1;      // int64: int4 = 2 entries {x=lo0, z=lo1}
            for (int e = i; e < nq; e += st) {
                int4 v = p[e];
                atomicAdd(&g_count[v.x], 1);
                atomicAdd(&g_count[v.z], 1);
            }
        } else {
            int nq = nk >> 2;
            for (int e = i; e < nq; e += st) {
                int4 v = p[e];
                atomicAdd(&g_count[v.x], 1);
                atomicAdd(&g_count[v.y], 1);
                atomicAdd(&g_count[v.z], 1);
                atomicAdd(&g_count[v.w], 1);
            }
        }
    } else {
        if (is64) {
            const long long* p = (const long long*)idxp;
            for (int e = i; e < nk; e += st) atomicAdd(&g_count[(int)p[e]], 1);
        } else {
            const int* p = (const int*)idxp;
            for (int e = i; e < nk; e += st) atomicAdd(&g_count[p[e]], 1);
        }
    }
}

// ---------------- K2: T1 = feat @ W1 + b1 via HMMA, A-frags direct from GMEM ----
// 128 rows/block, 8 warps, warp w owns rows w*16..+15. No A smem staging.
__global__ __launch_bounds__(256, 3) void k_gemm1(const float* __restrict__ feat,
                                                  const float* __restrict__ W1,
                                                  const float* __restrict__ b1, int n) {
    __shared__ __half Bs[64 * 72];
    __shared__ float  bias[64];
    __shared__ float  shs[8 * 64], shq[8 * 64];

    int tid = threadIdx.x;
    // Bs <- f16(W1)
    for (int t = tid; t < 64 * 16; t += 256) {
        int r = t >> 4, q = t & 15;
        float4 v = ((const float4*)W1)[t];
        __half2 h0 = __floats2half2_rn(v.x, v.y);
        __half2 h1 = __floats2half2_rn(v.z, v.w);
        uint2 pk; pk.x = *(uint32_t*)&h0; pk.y = *(uint32_t*)&h1;
        *(uint2*)&Bs[r * 72 + q * 4] = pk;
    }
    if (tid < 64) bias[tid] = b1[tid];
    __syncthreads();

    int w = tid >> 5, lane = tid & 31;
    int rq = lane >> 2, cq = lane & 3;
    int rt = blockIdx.x * 128 + w * 16;
    int lr = (lane & 7) + ((lane >> 3) & 1) * 8;
    int lc = (lane >> 4) * 8;
    uint32_t bbase = smem_u32(Bs);

    int r0 = rt + rq, r1 = rt + rq + 8;
    bool v0 = r0 < n, v1 = r1 < n;
    const float2* f0 = (const float2*)(feat + (size_t)(v0 ? r0 : 0) * CIN);
    const float2* f1 = (const float2*)(feat + (size_t)(v1 ? r1 : 0) * CIN);
    const float2 z2 = make_float2(0.f, 0.f);

    float acc[8][4];
#pragma unroll
    for (int i = 0; i < 8; i++)
#pragma unroll
        for (int j = 0; j < 4; j++) acc[i][j] = 0.0f;

    // buf[.][f]: f0=(r0,klo) f1=(r1,klo) f2=(r0,khi) f3=(r1,khi)
    float2 buf[2][4];
    {
        int cidx = cq;
        buf[0][0] = v0 ? f0[cidx]     : z2;
        buf[0][1] = v1 ? f1[cidx]     : z2;
        buf[0][2] = v0 ? f0[cidx + 4] : z2;
        buf[0][3] = v1 ? f1[cidx + 4] : z2;
    }
#pragma unroll
    for (int kc = 0; kc < 4; kc++) {
        if (kc < 3) {
            int cidx = (kc + 1) * 8 + cq;
            float2* d = buf[(kc + 1) & 1];
            d[0] = v0 ? f0[cidx]     : z2;
            d[1] = v1 ? f1[cidx]     : z2;
            d[2] = v0 ? f0[cidx + 4] : z2;
            d[3] = v1 ? f1[cidx + 4] : z2;
        }
        uint32_t A[4];
#pragma unroll
        for (int f = 0; f < 4; f++) {
            __half2 h = __floats2half2_rn(buf[kc & 1][f].x, buf[kc & 1][f].y);
            A[f] = *(uint32_t*)&h;
        }
        int k0 = kc * 16;
#pragma unroll
        for (int nt2 = 0; nt2 < 4; nt2++) {
            uint32_t b0, b1v, b2, b3;
            LDMX4T(b0, b1v, b2, b3, bbase + (uint32_t)(((k0 + lr) * 72 + nt2 * 16 + lc) * 2));
            MMA16816(acc[nt2 * 2],     A[0], A[1], A[2], A[3], b0, b1v);
            MMA16816(acc[nt2 * 2 + 1], A[0], A[1], A[2], A[3], b2, b3);
        }
    }

    // epilogue: store fp16 T1 + weighted stats
    float w0 = v0 ? (float)g_count[r0] : 0.f;
    float w1 = v1 ? (float)g_count[r1] : 0.f;
    int cb = cq * 2;
#pragma unroll
    for (int nt = 0; nt < 8; nt++) {
        int c = nt * 8 + cb;
        float bx = bias[c], by = bias[c + 1];
        float x0 = acc[nt][0] + bx, x1 = acc[nt][1] + by;
        float x2 = acc[nt][2] + bx, x3 = acc[nt][3] + by;
        if (v0) {
            __half2 h = __floats2half2_rn(x0, x1);
            *(__half2*)&g_T1h[(size_t)r0 * CMID + c] = h;
        }
        if (v1) {
            __half2 h = __floats2half2_rn(x2, x3);
            *(__half2*)&g_T1h[(size_t)r1 * CMID + c] = h;
        }
        float s0 = w0 * x0 + w1 * x2, s1 = w0 * x1 + w1 * x3;
        float q0 = w0 * x0 * x0 + w1 * x2 * x2, q1 = w0 * x1 * x1 + w1 * x3 * x3;
#pragma unroll
        for (int m = 4; m < 32; m <<= 1) {
            s0 += __shfl_xor_sync(0xffffffffu, s0, m);
            s1 += __shfl_xor_sync(0xffffffffu, s1, m);
            q0 += __shfl_xor_sync(0xffffffffu, q0, m);
            q1 += __shfl_xor_sync(0xffffffffu, q1, m);
        }
        if (lane < 4) {
            shs[w * 64 + c] = s0;  shs[w * 64 + c + 1] = s1;
            shq[w * 64 + c] = q0;  shq[w * 64 + c + 1] = q1;
        }
    }
    __syncthreads();
    if (tid < 64) {
        double s = 0.0, q = 0.0;
#pragma unroll
        for (int u = 0; u < 8; u++) { s += (double)shs[u * 64 + tid]; q += (double)shq[u * 64 + tid]; }
        int slot = blockIdx.x & (NSLOT - 1);
        atomicAdd(&g_sum1[slot * CMID + tid], s);
        atomicAdd(&g_sq1[slot * CMID + tid], q);
    }
}

// ---------------- K4: T2 = relu(bn1(T1)) @ W2 + b2 via HMMA, A-frags from GMEM ---
// 128 rows/block, 8 warps, warp w owns rows w*16..+15, loops 2 col-halves.
// BN1 affine computed per-block from global sums (kernel boundary = sync).
__global__ __launch_bounds__(256, 3) void k_gemm2(const float* __restrict__ W2,
                                                  const float* __restrict__ b2,
                                                  const float* __restrict__ g1,
                                                  const float* __restrict__ be1,
                                                  double M, int n) {
    __shared__ __half Bs[64 * 136];
    __shared__ float  bias[128];
    __shared__ float  s1s[64], t1s[64];
    __shared__ float  shs[8 * 128], shq[8 * 128];

    int tid = threadIdx.x;
    // BN1 affine from accumulated sums (identical math to old k_fin)
    if (tid < 64) {
        double s = 0.0, q = 0.0;
#pragma unroll
        for (int u = 0; u < NSLOT; u++) { s += g_sum1[u * CMID + tid]; q += g_sq1[u * CMID + tid]; }
        double mean = s / M;
        double var  = q / M - mean * mean;
        double rs   = 1.0 / sqrt(var + BN_EPS);
        float  sc   = (float)((double)g1[tid] * rs);
        s1s[tid] = sc;
        t1s[tid] = (float)((double)be1[tid] - mean * (double)sc);
    }
    // Bs <- f16(W2); stride 136 halves (272B)
    for (int t = tid; t < 64 * 32; t += 256) {
        int r = t >> 5, q = t & 31;
        float4 v = ((const float4*)W2)[t];
        __half2 h0 = __floats2half2_rn(v.x, v.y);
        __half2 h1 = __floats2half2_rn(v.z, v.w);
        uint2 pk; pk.x = *(uint32_t*)&h0; pk.y = *(uint32_t*)&h1;
        *(uint2*)&Bs[r * 136 + q * 4] = pk;
    }
    if (tid < 128) bias[tid] = b2[tid];
    __syncthreads();

    int w = tid >> 5, lane = tid & 31;
    int rq = lane >> 2, cq = lane & 3;
    int rt = blockIdx.x * 128 + w * 16;
    int lr = (lane & 7) + ((lane >> 3) & 1) * 8;
    int lc = (lane >> 4) * 8;
    uint32_t bbase = smem_u32(Bs);

    int r0 = rt + rq, r1 = rt + rq + 8;
    bool v0 = r0 < n, v1 = r1 < n;
    const uint32_t* t0 = (const uint32_t*)(g_T1h + (size_t)(v0 ? r0 : 0) * CMID);
    const uint32_t* t1p = (const uint32_t*)(g_T1h + (size_t)(v1 ? r1 : 0) * CMID);

    // Build all A fragments (relu(bn1(T1))) once: af[kc][f], 16 regs
    uint32_t af[4][4];
#pragma unroll
    for (int kc = 0; kc < 4; kc++) {
#pragma unroll
        for (int f = 0; f < 4; f++) {
            int col = kc * 16 + ((f >> 1) << 3) + 2 * cq;
            bool vv = (f & 1) ? v1 : v0;
            uint32_t raw = vv ? ((f & 1) ? t1p[col >> 1] : t0[col >> 1]) : 0u;
            float2 fv = __half22float2(*(__half2*)&raw);
            float2 s = *(const float2*)&s1s[col];
            float2 t = *(const float2*)&t1s[col];
            fv.x = fmaxf(fmaf(s.x, fv.x, t.x), 0.0f);
            fv.y = fmaxf(fmaf(s.y, fv.y, t.y), 0.0f);
            __half2 h = __floats2half2_rn(fv.x, fv.y);
            af[kc][f] = *(uint32_t*)&h;
        }
    }

    float w0 = v0 ? (float)g_count[r0] : 0.f;
    float w1 = v1 ? (float)g_count[r1] : 0.f;
    int cbq = cq * 2;

#pragma unroll
    for (int half = 0; half < 2; half++) {
        float acc[8][4];
#pragma unroll
        for (int i = 0; i < 8; i++)
#pragma unroll
            for (int j = 0; j < 4; j++) acc[i][j] = 0.0f;

#pragma unroll
        for (int kc = 0; kc < 4; kc++) {
            int k0 = kc * 16;
#pragma unroll
            for (int nt2 = 0; nt2 < 4; nt2++) {
                uint32_t b0, b1v, b2, b3;
                LDMX4T(b0, b1v, b2, b3,
                       bbase + (uint32_t)(((k0 + lr) * 136 + half * 64 + nt2 * 16 + lc) * 2));
                MMA16816(acc[nt2 * 2],     af[kc][0], af[kc][1], af[kc][2], af[kc][3], b0, b1v);
                MMA16816(acc[nt2 * 2 + 1], af[kc][0], af[kc][1], af[kc][2], af[kc][3], b2, b3);
            }
        }

        // epilogue: store fp16 T2 (pre-BN2) + weighted stats
#pragma unroll
        for (int nt = 0; nt < 8; nt++) {
            int c = half * 64 + nt * 8 + cbq;
            float bx = bias[c], by = bias[c + 1];
            float x0 = acc[nt][0] + bx, x1 = acc[nt][1] + by;
            float x2 = acc[nt][2] + bx, x3 = acc[nt][3] + by;
            if (v0) {
                __half2 h = __floats2half2_rn(x0, x1);
                *(__half2*)&g_T2h[(size_t)r0 * COUT + c] = h;
            }
            if (v1) {
                __half2 h = __floats2half2_rn(x2, x3);
                *(__half2*)&g_T2h[(size_t)r1 * COUT + c] = h;
            }
            float s0 = w0 * x0 + w1 * x2, s1 = w0 * x1 + w1 * x3;
            float q0 = w0 * x0 * x0 + w1 * x2 * x2, q1 = w0 * x1 * x1 + w1 * x3 * x3;
#pragma unroll
            for (int m = 4; m < 32; m <<= 1) {
                s0 += __shfl_xor_sync(0xffffffffu, s0, m);
                s1 += __shfl_xor_sync(0xffffffffu, s1, m);
                q0 += __shfl_xor_sync(0xffffffffu, q0, m);
                q1 += __shfl_xor_sync(0xffffffffu, q1, m);
            }
            if (lane < 4) {
                shs[w * 128 + c] = s0;  shs[w * 128 + c + 1] = s1;
                shq[w * 128 + c] = q0;  shq[w * 128 + c + 1] = q1;
            }
        }
    }
    __syncthreads();
    if (tid < 128) {
        double s = 0.0, q = 0.0;
#pragma unroll
        for (int u = 0; u < 8; u++) { s += (double)shs[u * 128 + tid]; q += (double)shq[u * 128 + tid]; }
        int slot = blockIdx.x & (NSLOT - 1);
        atomicAdd(&g_sum2[slot * COUT + tid], s);
        atomicAdd(&g_sq2[slot * COUT + tid], q);
    }
}

// ---------------- K6: gather + bn2 affine + relu + max over k (fp16 table) -------
// One warp per output point. BN2 affine computed per-block from global sums.
__global__ __launch_bounds__(256) void k_gather(const void* __restrict__ idxp,
                                                float* __restrict__ out,
                                                const float* __restrict__ g2,
                                                const float* __restrict__ be2,
                                                double M, int n, int k) {
    __shared__ float s2s[COUT], t2s[COUT];
    int tid = threadIdx.x;
    if (tid < COUT) {
        double s = 0.0, q = 0.0;
#pragma unroll
        for (int u = 0; u < NSLOT; u++) { s += g_sum2[u * COUT + tid]; q += g_sq2[u * COUT + tid]; }
        double mean = s / M;
        double var  = q / M - mean * mean;
        double rs   = 1.0 / sqrt(var + BN_EPS);
        float  sc   = (float)((double)g2[tid] * rs);
        s2s[tid] = sc;
        t2s[tid] = (float)((double)be2[tid] - mean * (double)sc);
    }
    __syncthreads();

    int warp = (blockIdx.x * blockDim.x + tid) >> 5;
    int lane = tid & 31;
    if (warp >= n) return;
    int is64 = g_is64;

    float4 s2 = *(const float4*)&s2s[lane * 4];
    float4 t2 = *(const float4*)&t2s[lane * 4];
    float m0 = 0.f, m1 = 0.f, m2 = 0.f, m3 = 0.f;   // relu => result >= 0

    if (k == 16) {
        int r_mine = 0;
        if (lane < 16) {
            if (is64) r_mine = (int)((const long long*)idxp)[(size_t)warp * 16 + lane];
            else      r_mine = ((const int*)idxp)[(size_t)warp * 16 + lane];
        }
#pragma unroll
        for (int j = 0; j < 16; j++) {
            int r = __shfl_sync(0xffffffffu, r_mine, j);
            uint2 v = *(const uint2*)&g_T2h[(size_t)r * COUT + lane * 4];
            float2 f01 = __half22float2(*(__half2*)&v.x);
            float2 f23 = __half22float2(*(__half2*)&v.y);
            m0 = fmaxf(m0, fmaf(s2.x, f01.x, t2.x));
            m1 = fmaxf(m1, fmaf(s2.y, f01.y, t2.y));
            m2 = fmaxf(m2, fmaf(s2.z, f23.x, t2.z));
            m3 = fmaxf(m3, fmaf(s2.w, f23.y, t2.w));
        }
    } else {
        for (int j = 0; j < k; j++) {
            int r;
            if (is64) r = (int)((const long long*)idxp)[(size_t)warp * k + j];
            else      r = ((const int*)idxp)[(size_t)warp * k + j];
            uint2 v = *(const uint2*)&g_T2h[(size_t)r * COUT + lane * 4];
            float2 f01 = __half22float2(*(__half2*)&v.x);
            float2 f23 = __half22float2(*(__half2*)&v.y);
            m0 = fmaxf(m0, fmaf(s2.x, f01.x, t2.x));
            m1 = fmaxf(m1, fmaf(s2.y, f01.y, t2.y));
            m2 = fmaxf(m2, fmaf(s2.z, f23.x, t2.z));
            m3 = fmaxf(m3, fmaf(s2.w, f23.y, t2.w));
        }
    }
    *(float4*)&out[(size_t)warp * COUT + lane * 4] = make_float4(m0, m1, m2, m3);
}

// ---------------- host launcher ----------------
extern "C" void kernel_launch(void* const* d_in, const int* in_sizes, int n_in,
                              void* d_out, int out_size) {
    const float* feat = (const float*)d_in[0];
    const void*  idx  = d_in[1];
    const float* W1   = (const float*)d_in[2];
    const float* b1   = (const float*)d_in[3];
    const float* g1   = (const float*)d_in[4];
    const float* be1  = (const float*)d_in[5];
    const float* W2   = (const float*)d_in[6];
    const float* b2   = (const float*)d_in[7];
    const float* g2   = (const float*)d_in[8];
    const float* be2  = (const float*)d_in[9];
    float* out = (float*)d_out;

    int n  = in_sizes[0] / CIN;      // 100000
    int nk = in_sizes[1];            // n * k
    int k  = nk / n;                 // 16
    double M = (double)nk;

    k_init<<<(n + 255) / 256, 256>>>((const int*)idx, nk, n);
    k_hist<<<512, 256>>>(idx, nk);

    k_gemm1<<<(n + 127) / 128, 256>>>(feat, W1, b1, n);
    k_gemm2<<<(n + 127) / 128, 256>>>(W2, b2, g1, be1, M, n);
    k_gather<<<(n + 7) / 8, 256>>>(idx, out, g2, be2, M, n, k);
}

// round 12
// speedup vs baseline: 2.5118x; 2.5118x over previous
#include <cuda_runtime.h>
#include <cuda_fp16.h>
#include <cstdint>

#define N_MAX 100000
#define CIN   64
#define CMID  64
#define COUT  128
#define BN_EPS 1e-5
#define NSLOT 16

// ---------------- mma / ldmatrix helpers (sm_103a HMMA path) ----------------
__device__ __forceinline__ uint32_t smem_u32(const void* p) {
    return (uint32_t)__cvta_generic_to_shared(p);
}
#define LDMX4T(r0, r1, r2, r3, addr) \
    asm volatile("ldmatrix.sync.aligned.m8n8.x4.trans.shared.b16 {%0,%1,%2,%3}, [%4];" \
                 : "=r"(r0), "=r"(r1), "=r"(r2), "=r"(r3) : "r"(addr))
#define MMA16816(d, a0, a1, a2, a3, b0, b1) \
    asm volatile("mma.sync.aligned.m16n8k16.row.col.f32.f16.f16.f32 " \
                 "{%0,%1,%2,%3}, {%4,%5,%6,%7}, {%8,%9}, {%0,%1,%2,%3};" \
                 : "+f"(d[0]), "+f"(d[1]), "+f"(d[2]), "+f"(d[3]) \
                 : "r"(a0), "r"(a1), "r"(a2), "r"(a3), "r"(b0), "r"(b1))

// ---------------- device scratch (static: no allocations allowed) ----------------
__device__ int    g_count[N_MAX];
__device__ __half g_T1h[(size_t)N_MAX * CMID];   // feat @ W1 + b1, fp16 (12.8 MB)
__device__ __half g_T2h[(size_t)N_MAX * COUT];   // T2 pre-BN2, fp16 (25.6 MB)
__device__ double g_sum1[NSLOT * CMID], g_sq1[NSLOT * CMID];
__device__ double g_sum2[NSLOT * COUT], g_sq2[NSLOT * COUT];
__device__ float  g_s1[CMID], g_t1[CMID];
__device__ float  g_s2[COUT], g_t2[COUT];
__device__ int    g_is64;
__device__ int    g_tick1, g_tick2;

// ---------------- K0: zero counters/accumulators/tickets + detect idx dtype -----
// idx in [0, n), n < 2^31. Little-endian int64 => every odd 32-bit word is 0.
__global__ void k_init(const int* w, int nk, int n) {
    int i  = blockIdx.x * blockDim.x + threadIdx.x;
    int st = gridDim.x * blockDim.x;
    for (int j = i; j < n; j += st) g_count[j] = 0;
    if (i < NSLOT * CMID) { g_sum1[i] = 0.0; g_sq1[i] = 0.0; }
    if (i < NSLOT * COUT) { g_sum2[i] = 0.0; g_sq2[i] = 0.0; }
    if (blockIdx.x == 0) {
        __shared__ int ok;
        if (threadIdx.x == 0) { ok = 1; g_tick1 = 0; g_tick2 = 0; }
        __syncthreads();
        int m = 64;
        if (nk < 128) m = nk / 2;
        if ((int)threadIdx.x < m) {
            if (w[2 * threadIdx.x + 1] != 0) ok = 0;  // benign race: only writes 0
        }
        __syncthreads();
        if (threadIdx.x == 0) g_is64 = ok;
    }
}

// ---------------- K1: histogram of idx (vectorized int4 loads) ----------------
__global__ void k_hist(const void* idxp, int nk) {
    int is64 = g_is64;
    int i  = blockIdx.x * blockDim.x + threadIdx.x;
    int st = gridDim.x * blockDim.x;
    if ((nk & 3) == 0) {
        const int4* p = (const int4*)idxp;
        if (is64) {
            int nq = nk >> 1;      // int64: int4 = 2 entries {x=lo0, z=lo1}
            for (int e = i; e < nq; e += st) {
                int4 v = p[e];
                atomicAdd(&g_count[v.x], 1);
                atomicAdd(&g_count[v.z], 1);
            }
        } else {
            int nq = nk >> 2;
            for (int e = i; e < nq; e += st) {
                int4 v = p[e];
                atomicAdd(&g_count[v.x], 1);
                atomicAdd(&g_count[v.y], 1);
                atomicAdd(&g_count[v.z], 1);
                atomicAdd(&g_count[v.w], 1);
            }
        }
    } else {
        if (is64) {
            const long long* p = (const long long*)idxp;
            for (int e = i; e < nk; e += st) atomicAdd(&g_count[(int)p[e]], 1);
        } else {
            const int* p = (const int*)idxp;
            for (int e = i; e < nk; e += st) atomicAdd(&g_count[p[e]], 1);
        }
    }
}

// ---------------- K2: T1 = feat @ W1 + b1 via HMMA, A-frags direct from GMEM ----
// 128 rows/block, 8 warps, warp w owns rows w*16..+15. No A smem staging.
// Last-arriving block finalizes BN1 affine (g_s1/g_t1) from accumulated stats.
__global__ __launch_bounds__(256, 3) void k_gemm1(const float* __restrict__ feat,
                                                  const float* __restrict__ W1,
                                                  const float* __restrict__ b1,
                                                  const float* __restrict__ g1,
                                                  const float* __restrict__ be1,
                                                  double M, int n) {
    __shared__ __half Bs[64 * 72];
    __shared__ float  bias[64];
    __shared__ float  shs[8 * 64], shq[8 * 64];
    __shared__ int    lastflag;

    int tid = threadIdx.x;
    // Bs <- f16(W1)
    for (int t = tid; t < 64 * 16; t += 256) {
        int r = t >> 4, q = t & 15;
        float4 v = ((const float4*)W1)[t];
        __half2 h0 = __floats2half2_rn(v.x, v.y);
        __half2 h1 = __floats2half2_rn(v.z, v.w);
        uint2 pk; pk.x = *(uint32_t*)&h0; pk.y = *(uint32_t*)&h1;
        *(uint2*)&Bs[r * 72 + q * 4] = pk;
    }
    if (tid < 64) bias[tid] = b1[tid];
    __syncthreads();

    int w = tid >> 5, lane = tid & 31;
    int rq = lane >> 2, cq = lane & 3;
    int rt = blockIdx.x * 128 + w * 16;
    int lr = (lane & 7) + ((lane >> 3) & 1) * 8;
    int lc = (lane >> 4) * 8;
    uint32_t bbase = smem_u32(Bs);

    int r0 = rt + rq, r1 = rt + rq + 8;
    bool v0 = r0 < n, v1 = r1 < n;
    const float2* f0 = (const float2*)(feat + (size_t)(v0 ? r0 : 0) * CIN);
    const float2* f1 = (const float2*)(feat + (size_t)(v1 ? r1 : 0) * CIN);
    const float2 z2 = make_float2(0.f, 0.f);

    float acc[8][4];
#pragma unroll
    for (int i = 0; i < 8; i++)
#pragma unroll
        for (int j = 0; j < 4; j++) acc[i][j] = 0.0f;

    // buf[.][f]: f0=(r0,klo) f1=(r1,klo) f2=(r0,khi) f3=(r1,khi)
    float2 buf[2][4];
    {
        int cidx = cq;
        buf[0][0] = v0 ? f0[cidx]     : z2;
        buf[0][1] = v1 ? f1[cidx]     : z2;
        buf[0][2] = v0 ? f0[cidx + 4] : z2;
        buf[0][3] = v1 ? f1[cidx + 4] : z2;
    }
#pragma unroll
    for (int kc = 0; kc < 4; kc++) {
        if (kc < 3) {
            int cidx = (kc + 1) * 8 + cq;
            float2* d = buf[(kc + 1) & 1];
            d[0] = v0 ? f0[cidx]     : z2;
            d[1] = v1 ? f1[cidx]     : z2;
            d[2] = v0 ? f0[cidx + 4] : z2;
            d[3] = v1 ? f1[cidx + 4] : z2;
        }
        uint32_t A[4];
#pragma unroll
        for (int f = 0; f < 4; f++) {
            __half2 h = __floats2half2_rn(buf[kc & 1][f].x, buf[kc & 1][f].y);
            A[f] = *(uint32_t*)&h;
        }
        int k0 = kc * 16;
#pragma unroll
        for (int nt2 = 0; nt2 < 4; nt2++) {
            uint32_t b0, b1v, b2, b3;
            LDMX4T(b0, b1v, b2, b3, bbase + (uint32_t)(((k0 + lr) * 72 + nt2 * 16 + lc) * 2));
            MMA16816(acc[nt2 * 2],     A[0], A[1], A[2], A[3], b0, b1v);
            MMA16816(acc[nt2 * 2 + 1], A[0], A[1], A[2], A[3], b2, b3);
        }
    }

    // epilogue: store fp16 T1 + weighted stats
    float w0 = v0 ? (float)g_count[r0] : 0.f;
    float w1 = v1 ? (float)g_count[r1] : 0.f;
    int cb = cq * 2;
#pragma unroll
    for (int nt = 0; nt < 8; nt++) {
        int c = nt * 8 + cb;
        float bx = bias[c], by = bias[c + 1];
        float x0 = acc[nt][0] + bx, x1 = acc[nt][1] + by;
        float x2 = acc[nt][2] + bx, x3 = acc[nt][3] + by;
        if (v0) {
            __half2 h = __floats2half2_rn(x0, x1);
            *(__half2*)&g_T1h[(size_t)r0 * CMID + c] = h;
        }
        if (v1) {
            __half2 h = __floats2half2_rn(x2, x3);
            *(__half2*)&g_T1h[(size_t)r1 * CMID + c] = h;
        }
        float s0 = w0 * x0 + w1 * x2, s1 = w0 * x1 + w1 * x3;
        float q0 = w0 * x0 * x0 + w1 * x2 * x2, q1 = w0 * x1 * x1 + w1 * x3 * x3;
#pragma unroll
        for (int m = 4; m < 32; m <<= 1) {
            s0 += __shfl_xor_sync(0xffffffffu, s0, m);
            s1 += __shfl_xor_sync(0xffffffffu, s1, m);
            q0 += __shfl_xor_sync(0xffffffffu, q0, m);
            q1 += __shfl_xor_sync(0xffffffffu, q1, m);
        }
        if (lane < 4) {
            shs[w * 64 + c] = s0;  shs[w * 64 + c + 1] = s1;
            shq[w * 64 + c] = q0;  shq[w * 64 + c + 1] = q1;
        }
    }
    __syncthreads();
    if (tid < 64) {
        double s = 0.0, q = 0.0;
#pragma unroll
        for (int u = 0; u < 8; u++) { s += (double)shs[u * 64 + tid]; q += (double)shq[u * 64 + tid]; }
        int slot = blockIdx.x & (NSLOT - 1);
        atomicAdd(&g_sum1[slot * CMID + tid], s);
        atomicAdd(&g_sq1[slot * CMID + tid], q);
    }
    // last-block finalize: compute BN1 affine once
    __threadfence();
    __syncthreads();
    if (tid == 0) lastflag = (atomicAdd(&g_tick1, 1) == (int)gridDim.x - 1);
    __syncthreads();
    if (lastflag && tid < 64) {
        double s = 0.0, q = 0.0;
#pragma unroll
        for (int u = 0; u < NSLOT; u++) { s += g_sum1[u * CMID + tid]; q += g_sq1[u * CMID + tid]; }
        double mean = s / M;
        double var  = q / M - mean * mean;
        double rs   = 1.0 / sqrt(var + BN_EPS);
        float  sc   = (float)((double)g1[tid] * rs);
        g_s1[tid] = sc;
        g_t1[tid] = (float)((double)be1[tid] - mean * (double)sc);
    }
}

// ---------------- K4: T2 = relu(bn1(T1)) @ W2 + b2 via HMMA, A-frags from GMEM ---
// 128 rows/block, 8 warps, warp w owns rows w*16..+15, loops 2 col-halves.
// Last-arriving block finalizes BN2 affine (g_s2/g_t2).
__global__ __launch_bounds__(256, 3) void k_gemm2(const float* __restrict__ W2,
                                                  const float* __restrict__ b2,
                                                  const float* __restrict__ g2,
                                                  const float* __restrict__ be2,
                                                  double M, int n) {
    __shared__ __half Bs[64 * 136];
    __shared__ float  bias[128];
    __shared__ float  s1s[64], t1s[64];
    __shared__ float  shs[8 * 128], shq[8 * 128];
    __shared__ int    lastflag;

    int tid = threadIdx.x;
    // Bs <- f16(W2); stride 136 halves (272B)
    for (int t = tid; t < 64 * 32; t += 256) {
        int r = t >> 5, q = t & 31;
        float4 v = ((const float4*)W2)[t];
        __half2 h0 = __floats2half2_rn(v.x, v.y);
        __half2 h1 = __floats2half2_rn(v.z, v.w);
        uint2 pk; pk.x = *(uint32_t*)&h0; pk.y = *(uint32_t*)&h1;
        *(uint2*)&Bs[r * 136 + q * 4] = pk;
    }
    if (tid < 128) bias[tid] = b2[tid];
    if (tid < 64) { s1s[tid] = g_s1[tid]; t1s[tid] = g_t1[tid]; }
    __syncthreads();

    int w = tid >> 5, lane = tid & 31;
    int rq = lane >> 2, cq = lane & 3;
    int rt = blockIdx.x * 128 + w * 16;
    int lr = (lane & 7) + ((lane >> 3) & 1) * 8;
    int lc = (lane >> 4) * 8;
    uint32_t bbase = smem_u32(Bs);

    int r0 = rt + rq, r1 = rt + rq + 8;
    bool v0 = r0 < n, v1 = r1 < n;
    const uint32_t* t0 = (const uint32_t*)(g_T1h + (size_t)(v0 ? r0 : 0) * CMID);
    const uint32_t* t1p = (const uint32_t*)(g_T1h + (size_t)(v1 ? r1 : 0) * CMID);

    // Build all A fragments (relu(bn1(T1))) once: af[kc][f], 16 regs
    uint32_t af[4][4];
#pragma unroll
    for (int kc = 0; kc < 4; kc++) {
#pragma unroll
        for (int f = 0; f < 4; f++) {
            int col = kc * 16 + ((f >> 1) << 3) + 2 * cq;
            bool vv = (f & 1) ? v1 : v0;
            uint32_t raw = vv ? ((f & 1) ? t1p[col >> 1] : t0[col >> 1]) : 0u;
            float2 fv = __half22float2(*(__half2*)&raw);
            float2 s = *(const float2*)&s1s[col];
            float2 t = *(const float2*)&t1s[col];
            fv.x = fmaxf(fmaf(s.x, fv.x, t.x), 0.0f);
            fv.y = fmaxf(fmaf(s.y, fv.y, t.y), 0.0f);
            __half2 h = __floats2half2_rn(fv.x, fv.y);
            af[kc][f] = *(uint32_t*)&h;
        }
    }

    float w0 = v0 ? (float)g_count[r0] : 0.f;
    float w1 = v1 ? (float)g_count[r1] : 0.f;
    int cbq = cq * 2;

#pragma unroll
    for (int half = 0; half < 2; half++) {
        float acc[8][4];
#pragma unroll
        for (int i = 0; i < 8; i++)
#pragma unroll
            for (int j = 0; j < 4; j++) acc[i][j] = 0.0f;

#pragma unroll
        for (int kc = 0; kc < 4; kc++) {
            int k0 = kc * 16;
#pragma unroll
            for (int nt2 = 0; nt2 < 4; nt2++) {
                uint32_t b0, b1v, b2, b3;
                LDMX4T(b0, b1v, b2, b3,
                       bbase + (uint32_t)(((k0 + lr) * 136 + half * 64 + nt2 * 16 + lc) * 2));
                MMA16816(acc[nt2 * 2],     af[kc][0], af[kc][1], af[kc][2], af[kc][3], b0, b1v);
                MMA16816(acc[nt2 * 2 + 1], af[kc][0], af[kc][1], af[kc][2], af[kc][3], b2, b3);
            }
        }

        // epilogue: store fp16 T2 (pre-BN2) + weighted stats
#pragma unroll
        for (int nt = 0; nt < 8; nt++) {
            int c = half * 64 + nt * 8 + cbq;
            float bx = bias[c], by = bias[c + 1];
            float x0 = acc[nt][0] + bx, x1 = acc[nt][1] + by;
            float x2 = acc[nt][2] + bx, x3 = acc[nt][3] + by;
            if (v0) {
                __half2 h = __floats2half2_rn(x0, x1);
                *(__half2*)&g_T2h[(size_t)r0 * COUT + c] = h;
            }
            if (v1) {
                __half2 h = __floats2half2_rn(x2, x3);
                *(__half2*)&g_T2h[(size_t)r1 * COUT + c] = h;
            }
            float s0 = w0 * x0 + w1 * x2, s1 = w0 * x1 + w1 * x3;
            float q0 = w0 * x0 * x0 + w1 * x2 * x2, q1 = w0 * x1 * x1 + w1 * x3 * x3;
#pragma unroll
            for (int m = 4; m < 32; m <<= 1) {
                s0 += __shfl_xor_sync(0xffffffffu, s0, m);
                s1 += __shfl_xor_sync(0xffffffffu, s1, m);
                q0 += __shfl_xor_sync(0xffffffffu, q0, m);
                q1 += __shfl_xor_sync(0xffffffffu, q1, m);
            }
            if (lane < 4) {
                shs[w * 128 + c] = s0;  shs[w * 128 + c + 1] = s1;
                shq[w * 128 + c] = q0;  shq[w * 128 + c + 1] = q1;
            }
        }
    }
    __syncthreads();
    if (tid < 128) {
        double s = 0.0, q = 0.0;
#pragma unroll
        for (int u = 0; u < 8; u++) { s += (double)shs[u * 128 + tid]; q += (double)shq[u * 128 + tid]; }
        int slot = blockIdx.x & (NSLOT - 1);
        atomicAdd(&g_sum2[slot * COUT + tid], s);
        atomicAdd(&g_sq2[slot * COUT + tid], q);
    }
    // last-block finalize: compute BN2 affine once
    __threadfence();
    __syncthreads();
    if (tid == 0) lastflag = (atomicAdd(&g_tick2, 1) == (int)gridDim.x - 1);
    __syncthreads();
    if (lastflag && tid < 128) {
        double s = 0.0, q = 0.0;
#pragma unroll
        for (int u = 0; u < NSLOT; u++) { s += g_sum2[u * COUT + tid]; q += g_sq2[u * COUT + tid]; }
        double mean = s / M;
        double var  = q / M - mean * mean;
        double rs   = 1.0 / sqrt(var + BN_EPS);
        float  sc   = (float)((double)g2[tid] * rs);
        g_s2[tid] = sc;
        g_t2[tid] = (float)((double)be2[tid] - mean * (double)sc);
    }
}

// ---------------- K6: gather + bn2 affine + relu + max over k (fp16 table) -------
// One warp per output point. Lane l owns channels 4l..4l+3.
__global__ __launch_bounds__(256) void k_gather(const void* __restrict__ idxp,
                                                float* __restrict__ out, int n, int k) {
    int warp = (blockIdx.x * blockDim.x + threadIdx.x) >> 5;
    int lane = threadIdx.x & 31;
    if (warp >= n) return;
    int is64 = g_is64;

    float4 s2 = *(const float4*)&g_s2[lane * 4];
    float4 t2 = *(const float4*)&g_t2[lane * 4];
    float m0 = 0.f, m1 = 0.f, m2 = 0.f, m3 = 0.f;   // relu => result >= 0

    if (k == 16) {
        int r_mine = 0;
        if (lane < 16) {
            if (is64) r_mine = (int)((const long long*)idxp)[(size_t)warp * 16 + lane];
            else      r_mine = ((const int*)idxp)[(size_t)warp * 16 + lane];
        }
#pragma unroll
        for (int j = 0; j < 16; j++) {
            int r = __shfl_sync(0xffffffffu, r_mine, j);
            uint2 v = *(const uint2*)&g_T2h[(size_t)r * COUT + lane * 4];
            float2 f01 = __half22float2(*(__half2*)&v.x);
            float2 f23 = __half22float2(*(__half2*)&v.y);
            m0 = fmaxf(m0, fmaf(s2.x, f01.x, t2.x));
            m1 = fmaxf(m1, fmaf(s2.y, f01.y, t2.y));
            m2 = fmaxf(m2, fmaf(s2.z, f23.x, t2.z));
            m3 = fmaxf(m3, fmaf(s2.w, f23.y, t2.w));
        }
    } else {
        for (int j = 0; j < k; j++) {
            int r;
            if (is64) r = (int)((const long long*)idxp)[(size_t)warp * k + j];
            else      r = ((const int*)idxp)[(size_t)warp * k + j];
            uint2 v = *(const uint2*)&g_T2h[(size_t)r * COUT + lane * 4];
            float2 f01 = __half22float2(*(__half2*)&v.x);
            float2 f23 = __half22float2(*(__half2*)&v.y);
            m0 = fmaxf(m0, fmaf(s2.x, f01.x, t2.x));
            m1 = fmaxf(m1, fmaf(s2.y, f01.y, t2.y));
            m2 = fmaxf(m2, fmaf(s2.z, f23.x, t2.z));
            m3 = fmaxf(m3, fmaf(s2.w, f23.y, t2.w));
        }
    }
    *(float4*)&out[(size_t)warp * COUT + lane * 4] = make_float4(m0, m1, m2, m3);
}

// ---------------- host launcher ----------------
extern "C" void kernel_launch(void* const* d_in, const int* in_sizes, int n_in,
                              void* d_out, int out_size) {
    const float* feat = (const float*)d_in[0];
    const void*  idx  = d_in[1];
    const float* W1   = (const float*)d_in[2];
    const float* b1   = (const float*)d_in[3];
    const float* g1   = (const float*)d_in[4];
    const float* be1  = (const float*)d_in[5];
    const float* W2   = (const float*)d_in[6];
    const float* b2   = (const float*)d_in[7];
    const float* g2   = (const float*)d_in[8];
    const float* be2  = (const float*)d_in[9];
    float* out = (float*)d_out;

    int n  = in_sizes[0] / CIN;      // 100000
    int nk = in_sizes[1];            // n * k
    int k  = nk / n;                 // 16
    double M = (double)nk;

    k_init<<<(n + 255) / 256, 256>>>((const int*)idx, nk, n);
    k_hist<<<512, 256>>>(idx, nk);

    k_gemm1<<<(n + 127) / 128, 256>>>(feat, W1, b1, g1, be1, M, n);
    k_gemm2<<<(n + 127) / 128, 256>>>(W2, b2, g2, be2, M, n);
    k_gather<<<(n + 7) / 8, 256>>>(idx, out, n, k);
}